// round 8
// baseline (speedup 1.0000x reference)
#include <cuda_runtime.h>
#include <math.h>

#define BB 8
#define SS 2048
#define HH 1024
#define NN 262144
#define DD 512
#define KK 8
#define TKB 128

__device__ float g_xpart[8 * BB * HH];
__device__ float g_q[BB * DD];
__device__ float g_scores[BB * NN];
__device__ float g_cand_v[BB * TKB * 8];
__device__ int   g_cand_i[BB * TKB * 8];
__device__ float g_Rt[BB * DD * KK];
__device__ float g_W2[BB * HH * KK];
__device__ float g_RO[BB * HH * KK];

__device__ __forceinline__ unsigned long long pack2(float lo, float hi) {
    unsigned long long r;
    asm("mov.b64 %0, {%1, %2};" : "=l"(r)
        : "r"(__float_as_uint(lo)), "r"(__float_as_uint(hi)));
    return r;
}
__device__ __forceinline__ void fma2(unsigned long long& d,
                                     unsigned long long a, unsigned long long b) {
    asm("fma.rn.f32x2 %0, %1, %2, %0;" : "+l"(d) : "l"(a), "l"(b));
}
__device__ __forceinline__ unsigned long long add2(unsigned long long a,
                                                   unsigned long long b) {
    unsigned long long r;
    asm("add.rn.f32x2 %0, %1, %2;" : "=l"(r) : "l"(a), "l"(b));
    return r;
}
__device__ __forceinline__ void unpack2(unsigned long long v, float& lo, float& hi) {
    unsigned int l, h;
    asm("mov.b64 {%0, %1}, %2;" : "=r"(l), "=r"(h) : "l"(v));
    lo = __uint_as_float(l); hi = __uint_as_float(h);
}

// ---------- Kernel A: partial sums of x over S (chunk=64 rows, 512 blocks/launch) ----------
__global__ void k_xpart(const float* __restrict__ x, int z0) {
    int h = blockIdx.x * 256 + threadIdx.x;  // grid.x = 4
    int b = blockIdx.y;
    int z = z0 + blockIdx.z;                  // 0..31 chunks of 64 rows
    const float* xp = x + ((size_t)b * SS + (size_t)z * 64) * HH + h;
    float s0 = 0.0f, s1 = 0.0f, s2 = 0.0f, s3 = 0.0f;
#pragma unroll 4
    for (int i = 0; i < 64; i += 4) {
        s0 += xp[(size_t)(i + 0) * HH];
        s1 += xp[(size_t)(i + 1) * HH];
        s2 += xp[(size_t)(i + 2) * HH];
        s3 += xp[(size_t)(i + 3) * HH];
    }
    // 32 chunks -> 8 slots of 4 chunks; 4 z-values share a slot but are
    // DIFFERENT blocks -> use per-chunk slots to stay race-free: [z4][sub]
    // simpler: store per chunk into 32-slot layout folded by k_query? keep 8
    // slots via atomic-free: each z writes its own slot (z>>2) only after
    // accumulating 4 sub-chunks? Not possible across blocks -> give each z a
    // quarter-slot: g_xpart has 8*BB*HH floats = 32 quarter-slots of BB*HH/4?
    // Clean solution: 32 chunks, 8 slots, slot = z>>2, sub = z&3 folded into
    // the h-partition: store at [slot][b][h] summed over its own 4 chunks is
    // not possible; instead store each chunk at [z&7][b][h] ADDING z>=8 parts
    // would race. -> Use 8 slots with z mapped so each slot gets exactly 4
    // consecutive chunks handled by ONE block: blockIdx.z selects slot, loop 4.
    (void)s0; (void)s1; (void)s2; (void)s3;
}

// Replaced by a clean version: one block handles 256 rows (4 sub-chunks) so
// each [z8] slot is written by exactly one block per (b,h).
__global__ void k_xpart2(const float* __restrict__ x, int z0) {
    int h = blockIdx.x * 256 + threadIdx.x;  // grid.x = 4
    int b = blockIdx.y;
    int z = z0 + blockIdx.z;                  // slot 0..7, 256 rows each
    const float* xp = x + ((size_t)b * SS + (size_t)z * 256) * HH + h;
    float s0 = 0.0f, s1 = 0.0f, s2 = 0.0f, s3 = 0.0f;
#pragma unroll 8
    for (int i = 0; i < 256; i += 4) {
        s0 += xp[(size_t)(i + 0) * HH];
        s1 += xp[(size_t)(i + 1) * HH];
        s2 += xp[(size_t)(i + 2) * HH];
        s3 += xp[(size_t)(i + 3) * HH];
    }
    g_xpart[(z * BB + b) * HH + h] = (s0 + s1) + (s2 + s3);
}

// ---------- Kernel B: q[b][d] = (sum_s x[b,s,:]) @ Wq ----------
__global__ void k_query(const float* __restrict__ Wq) {
    __shared__ float xs[HH];
    int b = blockIdx.y;
    for (int h = threadIdx.x; h < HH; h += 256) {
        float s = 0.0f;
#pragma unroll
        for (int z = 0; z < 8; z++) s += g_xpart[(z * BB + b) * HH + h];
        xs[h] = s;
    }
    __syncthreads();
    int d = blockIdx.x * 256 + threadIdx.x;  // grid.x = 2
    float acc = 0.0f;
#pragma unroll 4
    for (int h = 0; h < HH; h++) acc += xs[h] * Wq[(size_t)h * DD + d];
    g_q[b * DD + d] = acc;
}

// ---------- Kernel C: cosine scores (8-lane groups, row-pair f32x2, dup-q smem) ----------
__global__ void __launch_bounds__(128, 3) k_scores(const float* __restrict__ mem) {
    __shared__ unsigned long long qd[BB * 4 * 128];  // [b][c][d4] duplicated pairs, 32KB
    __shared__ float s_out[BB * 128];                // [b][row-in-block], 4KB
    int tid = threadIdx.x;
    for (int i = tid; i < BB * 4 * 128; i += 128) {
        int d4 = i & 127, c = (i >> 7) & 3, b = i >> 9;
        float v = g_q[b * DD + d4 * 4 + c];
        qd[i] = pack2(v, v);
    }
    __syncthreads();

    int w = tid >> 5, lane = tid & 31;
    int g = lane >> 3, e = lane & 7;
    int rowblk = blockIdx.x * 128;   // grid = 2048
    int rowloc = w * 32 + g * 8;
    size_t row0 = (size_t)rowblk + rowloc;
    const float4* m4 = (const float4*)mem;

    unsigned long long acc2[4][8];
    unsigned long long nrm2[4];
#pragma unroll
    for (int rp = 0; rp < 4; rp++) {
        nrm2[rp] = 0ull;
#pragma unroll
        for (int b = 0; b < 8; b++) acc2[rp][b] = 0ull;
    }

#pragma unroll
    for (int j = 0; j < 16; j++) {
        int d4 = e + 8 * j;
        float4 m[8];
#pragma unroll
        for (int r = 0; r < 8; r++)
            m[r] = m4[(row0 + r) * (DD / 4) + d4];

        unsigned long long mp[4][4];
#pragma unroll
        for (int rp = 0; rp < 4; rp++) {
            mp[rp][0] = pack2(m[2 * rp].x, m[2 * rp + 1].x);
            mp[rp][1] = pack2(m[2 * rp].y, m[2 * rp + 1].y);
            mp[rp][2] = pack2(m[2 * rp].z, m[2 * rp + 1].z);
            mp[rp][3] = pack2(m[2 * rp].w, m[2 * rp + 1].w);
        }
#pragma unroll
        for (int rp = 0; rp < 4; rp++) {
            fma2(nrm2[rp], mp[rp][0], mp[rp][0]);
            fma2(nrm2[rp], mp[rp][1], mp[rp][1]);
            fma2(nrm2[rp], mp[rp][2], mp[rp][2]);
            fma2(nrm2[rp], mp[rp][3], mp[rp][3]);
        }
#pragma unroll
        for (int b = 0; b < 8; b++) {
            unsigned long long q0 = qd[(b * 4 + 0) * 128 + d4];
            unsigned long long q1 = qd[(b * 4 + 1) * 128 + d4];
            unsigned long long q2 = qd[(b * 4 + 2) * 128 + d4];
            unsigned long long q3 = qd[(b * 4 + 3) * 128 + d4];
#pragma unroll
            for (int rp = 0; rp < 4; rp++) {
                fma2(acc2[rp][b], mp[rp][0], q0);
                fma2(acc2[rp][b], mp[rp][1], q1);
                fma2(acc2[rp][b], mp[rp][2], q2);
                fma2(acc2[rp][b], mp[rp][3], q3);
            }
        }
    }

#pragma unroll
    for (int off = 1; off <= 4; off <<= 1) {
#pragma unroll
        for (int rp = 0; rp < 4; rp++) {
            nrm2[rp] = add2(nrm2[rp], __shfl_xor_sync(0xffffffffu, nrm2[rp], off));
#pragma unroll
            for (int b = 0; b < 8; b++)
                acc2[rp][b] = add2(acc2[rp][b],
                                   __shfl_xor_sync(0xffffffffu, acc2[rp][b], off));
        }
    }
    if (e == 0) {
#pragma unroll
        for (int rp = 0; rp < 4; rp++) {
            float n0, n1;
            unpack2(nrm2[rp], n0, n1);
            float inv0 = 1.0f / (sqrtf(n0) + 1e-8f);
            float inv1 = 1.0f / (sqrtf(n1) + 1e-8f);
#pragma unroll
            for (int b = 0; b < 8; b++) {
                float a0, a1;
                unpack2(acc2[rp][b], a0, a1);
                s_out[b * 128 + rowloc + 2 * rp]     = a0 * inv0;
                s_out[b * 128 + rowloc + 2 * rp + 1] = a1 * inv1;
            }
        }
    }
    __syncthreads();
    {
        int b = tid >> 4, seg = tid & 15;
        const float4* src = (const float4*)&s_out[b * 128 + seg * 8];
        float4* dst = (float4*)&g_scores[(size_t)b * NN + rowblk + seg * 8];
        dst[0] = src[0];
        dst[1] = src[1];
    }
}

// ---------- Kernel D1: stage-1 top-8 ----------
__global__ void __launch_bounds__(256) k_topk1() {
    __shared__ float sv[256 * 8];
    __shared__ int   si[256 * 8];
    int b = blockIdx.y, blk = blockIdx.x, tid = threadIdx.x;
    int base = blk * (NN / TKB);
    const float4* s4 = (const float4*)(g_scores + (size_t)b * NN + base);

    float vals[8];
    int idxs[8];
#pragma unroll
    for (int i = 0; i < 8; i++) { vals[i] = -3.4e38f; idxs[i] = 0; }
    float vmin = -3.4e38f;

#pragma unroll
    for (int it = 0; it < 2; it++) {
        int f = tid + it * 256;
        float4 v4 = s4[f];
        int n0 = base + f * 4;
        float vv[4] = {v4.x, v4.y, v4.z, v4.w};
#pragma unroll
        for (int c = 0; c < 4; c++) {
            float v = vv[c];
            if (v > vmin) {
                vals[7] = v; idxs[7] = n0 + c;
#pragma unroll
                for (int p = 7; p >= 1; p--) {
                    if (vals[p] > vals[p - 1]) {
                        float tv = vals[p]; vals[p] = vals[p - 1]; vals[p - 1] = tv;
                        int ti = idxs[p]; idxs[p] = idxs[p - 1]; idxs[p - 1] = ti;
                    }
                }
                vmin = vals[7];
            }
        }
    }
#pragma unroll
    for (int i = 0; i < 8; i++) { sv[tid * 8 + i] = vals[i]; si[tid * 8 + i] = idxs[i]; }

    for (int stride = 128; stride >= 1; stride >>= 1) {
        __syncthreads();
        if (tid < stride) {
            float ov[8]; int oi[8];
            int ia = 0, ib2 = 0;
#pragma unroll
            for (int o = 0; o < 8; o++) {
                float va = sv[tid * 8 + ia];
                float vb = sv[(tid + stride) * 8 + ib2];
                if (va >= vb) { ov[o] = va; oi[o] = si[tid * 8 + ia]; ia++; }
                else          { ov[o] = vb; oi[o] = si[(tid + stride) * 8 + ib2]; ib2++; }
            }
#pragma unroll
            for (int o = 0; o < 8; o++) { sv[tid * 8 + o] = ov[o]; si[tid * 8 + o] = oi[o]; }
        }
    }
    __syncthreads();
    if (tid < 8) {
        g_cand_v[(b * TKB + blk) * 8 + tid] = sv[tid];
        g_cand_i[(b * TKB + blk) * 8 + tid] = si[tid];
    }
}

// ---------- Kernel D2+E1 fused: final merge + gather + normalize ----------
__global__ void __launch_bounds__(128) k_finish(const float* __restrict__ mem) {
    __shared__ float sv[128 * 8];
    __shared__ int   si[128 * 8];
    __shared__ int   s_idx[8];
    int b = blockIdx.x, tid = threadIdx.x;
#pragma unroll
    for (int i = 0; i < 8; i++) {
        sv[tid * 8 + i] = g_cand_v[(b * TKB + tid) * 8 + i];
        si[tid * 8 + i] = g_cand_i[(b * TKB + tid) * 8 + i];
    }
    for (int stride = 64; stride >= 1; stride >>= 1) {
        __syncthreads();
        if (tid < stride) {
            float ov[8]; int oi[8];
            int ia = 0, ib2 = 0;
#pragma unroll
            for (int o = 0; o < 8; o++) {
                float va = sv[tid * 8 + ia];
                float vb = sv[(tid + stride) * 8 + ib2];
                if (va >= vb) { ov[o] = va; oi[o] = si[tid * 8 + ia]; ia++; }
                else          { ov[o] = vb; oi[o] = si[(tid + stride) * 8 + ib2]; ib2++; }
            }
#pragma unroll
            for (int o = 0; o < 8; o++) { sv[tid * 8 + o] = ov[o]; si[tid * 8 + o] = oi[o]; }
        }
    }
    __syncthreads();
    if (tid < 8) s_idx[tid] = si[tid];
    __syncthreads();

    int w = tid >> 5, lane = tid & 31;
#pragma unroll
    for (int kk = 0; kk < 2; kk++) {
        int k = w * 2 + kk;
        int row = s_idx[k];
        const float4* r4 = (const float4*)(mem + (size_t)row * DD);
        float4 v[4];
        float nr = 0.0f;
#pragma unroll
        for (int jj = 0; jj < 4; jj++) {
            v[jj] = r4[lane + 32 * jj];
            nr += v[jj].x * v[jj].x + v[jj].y * v[jj].y
                + v[jj].z * v[jj].z + v[jj].w * v[jj].w;
        }
#pragma unroll
        for (int off = 16; off; off >>= 1)
            nr += __shfl_xor_sync(0xffffffffu, nr, off);
        float inv = 1.0f / (sqrtf(nr) + 1e-8f);
        float* Rt = g_Rt + (size_t)b * DD * 8;
#pragma unroll
        for (int jj = 0; jj < 4; jj++) {
            int d0 = (lane + 32 * jj) * 4;
            Rt[(d0 + 0) * 8 + k] = v[jj].x * inv;
            Rt[(d0 + 1) * 8 + k] = v[jj].y * inv;
            Rt[(d0 + 2) * 8 + k] = v[jj].z * inv;
            Rt[(d0 + 3) * 8 + k] = v[jj].w * inv;
        }
    }
}

// ---------- Kernel E2+E3 fused ----------
__global__ void __launch_bounds__(256) k_w2ro(const float* __restrict__ Wq,
                                              const float* __restrict__ Wo) {
    __shared__ float4 R_sh[DD * 2];
    int b = blockIdx.y;
    const float4* Rt4 = (const float4*)(g_Rt + (size_t)b * DD * 8);
    for (int i = threadIdx.x; i < DD * 2; i += 256) R_sh[i] = Rt4[i];
    __syncthreads();

    int h = blockIdx.x * 256 + threadIdx.x;
    float acc[8];
#pragma unroll
    for (int k = 0; k < 8; k++) acc[k] = 0.0f;

    if (blockIdx.z == 0) {
        const float4* wq4 = (const float4*)(Wq + (size_t)h * DD);
#pragma unroll 2
        for (int dd = 0; dd < DD / 4; dd++) {
            float4 wv4 = wq4[dd];
            float wv[4] = {wv4.x, wv4.y, wv4.z, wv4.w};
#pragma unroll
            for (int c = 0; c < 4; c++) {
                float4 r0 = R_sh[(dd * 4 + c) * 2];
                float4 r1 = R_sh[(dd * 4 + c) * 2 + 1];
                acc[0] += wv[c] * r0.x; acc[1] += wv[c] * r0.y;
                acc[2] += wv[c] * r0.z; acc[3] += wv[c] * r0.w;
                acc[4] += wv[c] * r1.x; acc[5] += wv[c] * r1.y;
                acc[6] += wv[c] * r1.z; acc[7] += wv[c] * r1.w;
            }
        }
        const float scale = 0.044194173824159216f;
        float4* o = (float4*)(g_W2 + ((size_t)b * HH + h) * 8);
        o[0] = make_float4(acc[0] * scale, acc[1] * scale, acc[2] * scale, acc[3] * scale);
        o[1] = make_float4(acc[4] * scale, acc[5] * scale, acc[6] * scale, acc[7] * scale);
    } else {
#pragma unroll 4
        for (int d = 0; d < DD; d++) {
            float wo = Wo[(size_t)d * HH + h];
            float4 r0 = R_sh[d * 2];
            float4 r1 = R_sh[d * 2 + 1];
            acc[0] += wo * r0.x; acc[1] += wo * r0.y; acc[2] += wo * r0.z; acc[3] += wo * r0.w;
            acc[4] += wo * r1.x; acc[5] += wo * r1.y; acc[6] += wo * r1.z; acc[7] += wo * r1.w;
        }
        float4* o = (float4*)(g_RO + ((size_t)b * HH + h) * 8);
        o[0] = make_float4(acc[0], acc[1], acc[2], acc[3]);
        o[1] = make_float4(acc[4], acc[5], acc[6], acc[7]);
    }
}

// ---------- Kernel F (fused): logits -> softmax -> out ----------
__global__ void __launch_bounds__(256) k_attn_out(const float* __restrict__ x,
                                                  float* __restrict__ out) {
    __shared__ float W2p[HH * 9];
    __shared__ float attn_sh[64 * 8];
    int b = blockIdx.y;
    const float* W2g = g_W2 + (size_t)b * HH * 8;
    for (int i = threadIdx.x; i < HH * 8; i += 256) {
        int h = i >> 3, k = i & 7;
        W2p[h * 9 + k] = W2g[i];
    }
    __syncthreads();

    int lane = threadIdx.x & 31, warp = threadIdx.x >> 5;
    int tok0 = blockIdx.x * 64 + warp * 8;
    const float* xb = x + ((size_t)b * SS + tok0) * HH;

    float lp[8][8];
#pragma unroll
    for (int t = 0; t < 8; t++)
#pragma unroll
        for (int k = 0; k < 8; k++) lp[t][k] = 0.0f;

#pragma unroll 4
    for (int i = 0; i < 32; i++) {
        int h = lane + 32 * i;
        float w2v[8];
#pragma unroll
        for (int k = 0; k < 8; k++) w2v[k] = W2p[h * 9 + k];
#pragma unroll
        for (int t = 0; t < 8; t++) {
            float xv = xb[(size_t)t * HH + h];
#pragma unroll
            for (int k = 0; k < 8; k++) lp[t][k] += xv * w2v[k];
        }
    }
#pragma unroll
    for (int off = 16; off; off >>= 1)
#pragma unroll
        for (int t = 0; t < 8; t++)
#pragma unroll
            for (int k = 0; k < 8; k++)
                lp[t][k] += __shfl_xor_sync(0xffffffffu, lp[t][k], off);

#pragma unroll
    for (int t = 0; t < 8; t++) {
        float l[8];
        float m = -3.4e38f;
#pragma unroll
        for (int k = 0; k < 8; k++) { l[k] = lp[t][k]; m = fmaxf(m, l[k]); }
        float s = 0.0f;
#pragma unroll
        for (int k = 0; k < 8; k++) { l[k] = __expf(l[k] - m); s += l[k]; }
        float inv = 1.0f / s;
        if (lane == t) {
            float4* a4 = (float4*)&attn_sh[(warp * 8 + t) * 8];
            a4[0] = make_float4(l[0] * inv, l[1] * inv, l[2] * inv, l[3] * inv);
            a4[1] = make_float4(l[4] * inv, l[5] * inv, l[6] * inv, l[7] * inv);
        }
    }
    __syncthreads();

    float att[8][8];
#pragma unroll
    for (int t = 0; t < 8; t++)
#pragma unroll
        for (int k = 0; k < 8; k++) att[t][k] = attn_sh[(warp * 8 + t) * 8 + k];

    const float4* ROg = (const float4*)(g_RO + (size_t)b * HH * 8);
    float* ob = out + ((size_t)b * SS + tok0) * HH;

#pragma unroll 2
    for (int i = 0; i < 32; i++) {
        int h = lane + 32 * i;
        float4 r0 = __ldg(&ROg[h * 2]);
        float4 r1 = __ldg(&ROg[h * 2 + 1]);
        float ro[8] = {r0.x, r0.y, r0.z, r0.w, r1.x, r1.y, r1.z, r1.w};
#pragma unroll
        for (int t = 0; t < 8; t++) {
            float o = xb[(size_t)t * HH + h];
#pragma unroll
            for (int k = 0; k < 8; k++) o += att[t][k] * ro[k];
            ob[(size_t)t * HH + h] = o;
        }
    }
}

// ---------- launch (correct dependency order; scores = 4th launch) ----------
extern "C" void kernel_launch(void* const* d_in, const int* in_sizes, int n_in,
                              void* d_out, int out_size) {
    const float* x   = (const float*)d_in[0];
    const float* mem = (const float*)d_in[1];
    const float* Wq  = (const float*)d_in[2];
    const float* Wo  = (const float*)d_in[3];
    float* out = (float*)d_out;

    k_xpart2  <<<dim3(4, 8, 4), 256>>>(x, 0);   // slots 0-3
    k_xpart2  <<<dim3(4, 8, 4), 256>>>(x, 4);   // slots 4-7
    k_query   <<<dim3(2, 8),    256>>>(Wq);
    k_scores  <<<2048,          128>>>(mem);    // 4th launch: ncu capture slot
    k_topk1   <<<dim3(TKB, 8),  256>>>();
    k_finish  <<<8,             128>>>(mem);
    k_w2ro    <<<dim3(4, 8, 2), 256>>>(Wq, Wo);
    k_attn_out<<<dim3(32, 8),   256>>>(x, out);
}

// round 9
// speedup vs baseline: 1.2840x; 1.2840x over previous
#include <cuda_runtime.h>
#include <math.h>

#define BB 8
#define SS 2048
#define HH 1024
#define NN 262144
#define DD 512
#define KK 8
#define TKB 128

__device__ float g_xpart[8 * BB * HH];
__device__ float g_q[BB * DD];
__device__ float g_scores[BB * NN];
__device__ float g_cand_v[BB * TKB * 8];
__device__ int   g_cand_i[BB * TKB * 8];
__device__ float g_Rt[BB * DD * KK];
__device__ float g_W2[BB * HH * KK];
__device__ float g_RO[BB * HH * KK];

__device__ __forceinline__ unsigned long long pack2(float lo, float hi) {
    unsigned long long r;
    asm("mov.b64 %0, {%1, %2};" : "=l"(r)
        : "r"(__float_as_uint(lo)), "r"(__float_as_uint(hi)));
    return r;
}
__device__ __forceinline__ void fma2(unsigned long long& d,
                                     unsigned long long a, unsigned long long b) {
    asm("fma.rn.f32x2 %0, %1, %2, %0;" : "+l"(d) : "l"(a), "l"(b));
}
__device__ __forceinline__ unsigned long long add2(unsigned long long a,
                                                   unsigned long long b) {
    unsigned long long r;
    asm("add.rn.f32x2 %0, %1, %2;" : "=l"(r) : "l"(a), "l"(b));
    return r;
}
__device__ __forceinline__ void unpack2(unsigned long long v, float& lo, float& hi) {
    unsigned int l, h;
    asm("mov.b64 {%0, %1}, %2;" : "=r"(l), "=r"(h) : "l"(v));
    lo = __uint_as_float(l); hi = __uint_as_float(h);
}

// ---------- Kernel A: partial sums of x over S ----------
__global__ void k_xpart2(const float* __restrict__ x, int z0) {
    int h = blockIdx.x * 256 + threadIdx.x;  // grid.x = 4
    int b = blockIdx.y;
    int z = z0 + blockIdx.z;                  // slot 0..7, 256 rows each
    const float* xp = x + ((size_t)b * SS + (size_t)z * 256) * HH + h;
    float s0 = 0.0f, s1 = 0.0f, s2 = 0.0f, s3 = 0.0f;
#pragma unroll 8
    for (int i = 0; i < 256; i += 4) {
        s0 += xp[(size_t)(i + 0) * HH];
        s1 += xp[(size_t)(i + 1) * HH];
        s2 += xp[(size_t)(i + 2) * HH];
        s3 += xp[(size_t)(i + 3) * HH];
    }
    g_xpart[(z * BB + b) * HH + h] = (s0 + s1) + (s2 + s3);
}

// ---------- Kernel B: q[b][d] = (sum_s x[b,s,:]) @ Wq ----------
__global__ void k_query(const float* __restrict__ Wq) {
    __shared__ float xs[HH];
    int b = blockIdx.y;
    for (int h = threadIdx.x; h < HH; h += 256) {
        float s = 0.0f;
#pragma unroll
        for (int z = 0; z < 8; z++) s += g_xpart[(z * BB + b) * HH + h];
        xs[h] = s;
    }
    __syncthreads();
    int d = blockIdx.x * 256 + threadIdx.x;  // grid.x = 2
    float acc = 0.0f;
#pragma unroll 4
    for (int h = 0; h < HH; h++) acc += xs[h] * Wq[(size_t)h * DD + d];
    g_q[b * DD + d] = acc;
}

// ---------- Kernel C: cosine scores v3 ----------
// 256 threads = 8 warps; warp = 4 groups of 8 lanes; group handles 4 rows.
// Block covers 128 rows. Row-pair f32x2 accumulators (norm packed too),
// 3-round 8-lane butterfly (10 SHFL-equiv/row vs 45 in the 32-lane scheme),
// duplicated-q smem (LDS.64 broadcast across groups), coalesced stores via smem.
__global__ void __launch_bounds__(256, 2) k_scores(const float* __restrict__ mem) {
    __shared__ unsigned long long qd[BB * 4 * 128];  // [b][c][d4] dup pairs, 32KB
    __shared__ float s_out[BB * 128];                // [b][row-in-block], 4KB
    int tid = threadIdx.x;
    for (int i = tid; i < BB * 4 * 128; i += 256) {
        int d4 = i & 127, c = (i >> 7) & 3, b = i >> 9;
        float v = g_q[b * DD + d4 * 4 + c];
        qd[i] = pack2(v, v);
    }
    __syncthreads();

    int w = tid >> 5, lane = tid & 31;
    int g = lane >> 3, e = lane & 7;
    int rowblk = blockIdx.x * 128;   // grid = 2048
    int rowloc = w * 16 + g * 4;     // group's 4 rows (local)
    size_t row0 = (size_t)rowblk + rowloc;
    const float4* m4 = (const float4*)mem;

    unsigned long long acc2[2][8];   // [row-pair][batch]
    unsigned long long nrm2[2];
#pragma unroll
    for (int rp = 0; rp < 2; rp++) {
        nrm2[rp] = 0ull;
#pragma unroll
        for (int b = 0; b < 8; b++) acc2[rp][b] = 0ull;
    }

#pragma unroll 2
    for (int j = 0; j < 16; j++) {
        int d4 = e + 8 * j;
        float4 m[4];
#pragma unroll
        for (int r = 0; r < 4; r++)
            m[r] = __ldcs(&m4[(row0 + r) * (DD / 4) + d4]);

        unsigned long long mp[2][4];
#pragma unroll
        for (int rp = 0; rp < 2; rp++) {
            mp[rp][0] = pack2(m[2 * rp].x, m[2 * rp + 1].x);
            mp[rp][1] = pack2(m[2 * rp].y, m[2 * rp + 1].y);
            mp[rp][2] = pack2(m[2 * rp].z, m[2 * rp + 1].z);
            mp[rp][3] = pack2(m[2 * rp].w, m[2 * rp + 1].w);
        }
#pragma unroll
        for (int rp = 0; rp < 2; rp++) {
            fma2(nrm2[rp], mp[rp][0], mp[rp][0]);
            fma2(nrm2[rp], mp[rp][1], mp[rp][1]);
            fma2(nrm2[rp], mp[rp][2], mp[rp][2]);
            fma2(nrm2[rp], mp[rp][3], mp[rp][3]);
        }
#pragma unroll
        for (int b = 0; b < 8; b++) {
            unsigned long long q0 = qd[(b * 4 + 0) * 128 + d4];
            unsigned long long q1 = qd[(b * 4 + 1) * 128 + d4];
            unsigned long long q2 = qd[(b * 4 + 2) * 128 + d4];
            unsigned long long q3 = qd[(b * 4 + 3) * 128 + d4];
#pragma unroll
            for (int rp = 0; rp < 2; rp++) {
                fma2(acc2[rp][b], mp[rp][0], q0);
                fma2(acc2[rp][b], mp[rp][1], q1);
                fma2(acc2[rp][b], mp[rp][2], q2);
                fma2(acc2[rp][b], mp[rp][3], q3);
            }
        }
    }

    // 3-round butterfly within each 8-lane group (4 groups in parallel)
#pragma unroll
    for (int off = 1; off <= 4; off <<= 1) {
#pragma unroll
        for (int rp = 0; rp < 2; rp++) {
            nrm2[rp] = add2(nrm2[rp], __shfl_xor_sync(0xffffffffu, nrm2[rp], off));
#pragma unroll
            for (int b = 0; b < 8; b++)
                acc2[rp][b] = add2(acc2[rp][b],
                                   __shfl_xor_sync(0xffffffffu, acc2[rp][b], off));
        }
    }
    if (e == 0) {
#pragma unroll
        for (int rp = 0; rp < 2; rp++) {
            float n0, n1;
            unpack2(nrm2[rp], n0, n1);
            float inv0 = 1.0f / (sqrtf(n0) + 1e-8f);
            float inv1 = 1.0f / (sqrtf(n1) + 1e-8f);
#pragma unroll
            for (int b = 0; b < 8; b++) {
                float a0, a1;
                unpack2(acc2[rp][b], a0, a1);
                s_out[b * 128 + rowloc + 2 * rp]     = a0 * inv0;
                s_out[b * 128 + rowloc + 2 * rp + 1] = a1 * inv1;
            }
        }
    }
    __syncthreads();
    // coalesced store: 256 threads x float4 = 4KB
    {
        int b = tid >> 5, seg = tid & 31;
        const float4* src = (const float4*)&s_out[b * 128 + seg * 4];
        float4* dst = (float4*)&g_scores[(size_t)b * NN + rowblk + seg * 4];
        dst[0] = src[0];
    }
}

// ---------- Kernel D1: stage-1 top-8 ----------
__global__ void __launch_bounds__(256) k_topk1() {
    __shared__ float sv[256 * 8];
    __shared__ int   si[256 * 8];
    int b = blockIdx.y, blk = blockIdx.x, tid = threadIdx.x;
    int base = blk * (NN / TKB);
    const float4* s4 = (const float4*)(g_scores + (size_t)b * NN + base);

    float vals[8];
    int idxs[8];
#pragma unroll
    for (int i = 0; i < 8; i++) { vals[i] = -3.4e38f; idxs[i] = 0; }
    float vmin = -3.4e38f;

#pragma unroll
    for (int it = 0; it < 2; it++) {
        int f = tid + it * 256;
        float4 v4 = s4[f];
        int n0 = base + f * 4;
        float vv[4] = {v4.x, v4.y, v4.z, v4.w};
#pragma unroll
        for (int c = 0; c < 4; c++) {
            float v = vv[c];
            if (v > vmin) {
                vals[7] = v; idxs[7] = n0 + c;
#pragma unroll
                for (int p = 7; p >= 1; p--) {
                    if (vals[p] > vals[p - 1]) {
                        float tv = vals[p]; vals[p] = vals[p - 1]; vals[p - 1] = tv;
                        int ti = idxs[p]; idxs[p] = idxs[p - 1]; idxs[p - 1] = ti;
                    }
                }
                vmin = vals[7];
            }
        }
    }
#pragma unroll
    for (int i = 0; i < 8; i++) { sv[tid * 8 + i] = vals[i]; si[tid * 8 + i] = idxs[i]; }

    for (int stride = 128; stride >= 1; stride >>= 1) {
        __syncthreads();
        if (tid < stride) {
            float ov[8]; int oi[8];
            int ia = 0, ib2 = 0;
#pragma unroll
            for (int o = 0; o < 8; o++) {
                float va = sv[tid * 8 + ia];
                float vb = sv[(tid + stride) * 8 + ib2];
                if (va >= vb) { ov[o] = va; oi[o] = si[tid * 8 + ia]; ia++; }
                else          { ov[o] = vb; oi[o] = si[(tid + stride) * 8 + ib2]; ib2++; }
            }
#pragma unroll
            for (int o = 0; o < 8; o++) { sv[tid * 8 + o] = ov[o]; si[tid * 8 + o] = oi[o]; }
        }
    }
    __syncthreads();
    if (tid < 8) {
        g_cand_v[(b * TKB + blk) * 8 + tid] = sv[tid];
        g_cand_i[(b * TKB + blk) * 8 + tid] = si[tid];
    }
}

// ---------- Kernel D2+E1 fused: final merge + gather + normalize ----------
__global__ void __launch_bounds__(128) k_finish(const float* __restrict__ mem) {
    __shared__ float sv[128 * 8];
    __shared__ int   si[128 * 8];
    __shared__ int   s_idx[8];
    int b = blockIdx.x, tid = threadIdx.x;
#pragma unroll
    for (int i = 0; i < 8; i++) {
        sv[tid * 8 + i] = g_cand_v[(b * TKB + tid) * 8 + i];
        si[tid * 8 + i] = g_cand_i[(b * TKB + tid) * 8 + i];
    }
    for (int stride = 64; stride >= 1; stride >>= 1) {
        __syncthreads();
        if (tid < stride) {
            float ov[8]; int oi[8];
            int ia = 0, ib2 = 0;
#pragma unroll
            for (int o = 0; o < 8; o++) {
                float va = sv[tid * 8 + ia];
                float vb = sv[(tid + stride) * 8 + ib2];
                if (va >= vb) { ov[o] = va; oi[o] = si[tid * 8 + ia]; ia++; }
                else          { ov[o] = vb; oi[o] = si[(tid + stride) * 8 + ib2]; ib2++; }
            }
#pragma unroll
            for (int o = 0; o < 8; o++) { sv[tid * 8 + o] = ov[o]; si[tid * 8 + o] = oi[o]; }
        }
    }
    __syncthreads();
    if (tid < 8) s_idx[tid] = si[tid];
    __syncthreads();

    int w = tid >> 5, lane = tid & 31;
#pragma unroll
    for (int kk = 0; kk < 2; kk++) {
        int k = w * 2 + kk;
        int row = s_idx[k];
        const float4* r4 = (const float4*)(mem + (size_t)row * DD);
        float4 v[4];
        float nr = 0.0f;
#pragma unroll
        for (int jj = 0; jj < 4; jj++) {
            v[jj] = r4[lane + 32 * jj];
            nr += v[jj].x * v[jj].x + v[jj].y * v[jj].y
                + v[jj].z * v[jj].z + v[jj].w * v[jj].w;
        }
#pragma unroll
        for (int off = 16; off; off >>= 1)
            nr += __shfl_xor_sync(0xffffffffu, nr, off);
        float inv = 1.0f / (sqrtf(nr) + 1e-8f);
        float* Rt = g_Rt + (size_t)b * DD * 8;
#pragma unroll
        for (int jj = 0; jj < 4; jj++) {
            int d0 = (lane + 32 * jj) * 4;
            Rt[(d0 + 0) * 8 + k] = v[jj].x * inv;
            Rt[(d0 + 1) * 8 + k] = v[jj].y * inv;
            Rt[(d0 + 2) * 8 + k] = v[jj].z * inv;
            Rt[(d0 + 3) * 8 + k] = v[jj].w * inv;
        }
    }
}

// ---------- Kernel E2+E3 fused ----------
__global__ void __launch_bounds__(256) k_w2ro(const float* __restrict__ Wq,
                                              const float* __restrict__ Wo) {
    __shared__ float4 R_sh[DD * 2];
    int b = blockIdx.y;
    const float4* Rt4 = (const float4*)(g_Rt + (size_t)b * DD * 8);
    for (int i = threadIdx.x; i < DD * 2; i += 256) R_sh[i] = Rt4[i];
    __syncthreads();

    int h = blockIdx.x * 256 + threadIdx.x;
    float acc[8];
#pragma unroll
    for (int k = 0; k < 8; k++) acc[k] = 0.0f;

    if (blockIdx.z == 0) {
        const float4* wq4 = (const float4*)(Wq + (size_t)h * DD);
#pragma unroll 2
        for (int dd = 0; dd < DD / 4; dd++) {
            float4 wv4 = wq4[dd];
            float wv[4] = {wv4.x, wv4.y, wv4.z, wv4.w};
#pragma unroll
            for (int c = 0; c < 4; c++) {
                float4 r0 = R_sh[(dd * 4 + c) * 2];
                float4 r1 = R_sh[(dd * 4 + c) * 2 + 1];
                acc[0] += wv[c] * r0.x; acc[1] += wv[c] * r0.y;
                acc[2] += wv[c] * r0.z; acc[3] += wv[c] * r0.w;
                acc[4] += wv[c] * r1.x; acc[5] += wv[c] * r1.y;
                acc[6] += wv[c] * r1.z; acc[7] += wv[c] * r1.w;
            }
        }
        const float scale = 0.044194173824159216f;  // 1/sqrt(512)
        float4* o = (float4*)(g_W2 + ((size_t)b * HH + h) * 8);
        o[0] = make_float4(acc[0] * scale, acc[1] * scale, acc[2] * scale, acc[3] * scale);
        o[1] = make_float4(acc[4] * scale, acc[5] * scale, acc[6] * scale, acc[7] * scale);
    } else {
#pragma unroll 4
        for (int d = 0; d < DD; d++) {
            float wo = Wo[(size_t)d * HH + h];
            float4 r0 = R_sh[d * 2];
            float4 r1 = R_sh[d * 2 + 1];
            acc[0] += wo * r0.x; acc[1] += wo * r0.y; acc[2] += wo * r0.z; acc[3] += wo * r0.w;
            acc[4] += wo * r1.x; acc[5] += wo * r1.y; acc[6] += wo * r1.z; acc[7] += wo * r1.w;
        }
        float4* o = (float4*)(g_RO + ((size_t)b * HH + h) * 8);
        o[0] = make_float4(acc[0], acc[1], acc[2], acc[3]);
        o[1] = make_float4(acc[4], acc[5], acc[6], acc[7]);
    }
}

// ---------- Kernel F (fused): logits -> softmax -> out ----------
__global__ void __launch_bounds__(256) k_attn_out(const float* __restrict__ x,
                                                  float* __restrict__ out) {
    __shared__ float W2p[HH * 9];
    __shared__ float attn_sh[64 * 8];
    int b = blockIdx.y;
    const float* W2g = g_W2 + (size_t)b * HH * 8;
    for (int i = threadIdx.x; i < HH * 8; i += 256) {
        int h = i >> 3, k = i & 7;
        W2p[h * 9 + k] = W2g[i];
    }
    __syncthreads();

    int lane = threadIdx.x & 31, warp = threadIdx.x >> 5;
    int tok0 = blockIdx.x * 64 + warp * 8;
    const float* xb = x + ((size_t)b * SS + tok0) * HH;

    float lp[8][8];
#pragma unroll
    for (int t = 0; t < 8; t++)
#pragma unroll
        for (int k = 0; k < 8; k++) lp[t][k] = 0.0f;

#pragma unroll 4
    for (int i = 0; i < 32; i++) {
        int h = lane + 32 * i;
        float w2v[8];
#pragma unroll
        for (int k = 0; k < 8; k++) w2v[k] = W2p[h * 9 + k];
#pragma unroll
        for (int t = 0; t < 8; t++) {
            float xv = xb[(size_t)t * HH + h];
#pragma unroll
            for (int k = 0; k < 8; k++) lp[t][k] += xv * w2v[k];
        }
    }
#pragma unroll
    for (int off = 16; off; off >>= 1)
#pragma unroll
        for (int t = 0; t < 8; t++)
#pragma unroll
            for (int k = 0; k < 8; k++)
                lp[t][k] += __shfl_xor_sync(0xffffffffu, lp[t][k], off);

#pragma unroll
    for (int t = 0; t < 8; t++) {
        float l[8];
        float m = -3.4e38f;
#pragma unroll
        for (int k = 0; k < 8; k++) { l[k] = lp[t][k]; m = fmaxf(m, l[k]); }
        float s = 0.0f;
#pragma unroll
        for (int k = 0; k < 8; k++) { l[k] = __expf(l[k] - m); s += l[k]; }
        float inv = 1.0f / s;
        if (lane == t) {
            float4* a4 = (float4*)&attn_sh[(warp * 8 + t) * 8];
            a4[0] = make_float4(l[0] * inv, l[1] * inv, l[2] * inv, l[3] * inv);
            a4[1] = make_float4(l[4] * inv, l[5] * inv, l[6] * inv, l[7] * inv);
        }
    }
    __syncthreads();

    float att[8][8];
#pragma unroll
    for (int t = 0; t < 8; t++)
#pragma unroll
        for (int k = 0; k < 8; k++) att[t][k] = attn_sh[(warp * 8 + t) * 8 + k];

    const float4* ROg = (const float4*)(g_RO + (size_t)b * HH * 8);
    float* ob = out + ((size_t)b * SS + tok0) * HH;

#pragma unroll 2
    for (int i = 0; i < 32; i++) {
        int h = lane + 32 * i;
        float4 r0 = __ldg(&ROg[h * 2]);
        float4 r1 = __ldg(&ROg[h * 2 + 1]);
        float ro[8] = {r0.x, r0.y, r0.z, r0.w, r1.x, r1.y, r1.z, r1.w};
#pragma unroll
        for (int t = 0; t < 8; t++) {
            float o = xb[(size_t)t * HH + h];
#pragma unroll
            for (int k = 0; k < 8; k++) o += att[t][k] * ro[k];
            ob[(size_t)t * HH + h] = o;
        }
    }
}

// ---------- launch (scores = 4th launch for the ncu capture slot) ----------
extern "C" void kernel_launch(void* const* d_in, const int* in_sizes, int n_in,
                              void* d_out, int out_size) {
    const float* x   = (const float*)d_in[0];
    const float* mem = (const float*)d_in[1];
    const float* Wq  = (const float*)d_in[2];
    const float* Wo  = (const float*)d_in[3];
    float* out = (float*)d_out;

    k_xpart2  <<<dim3(4, 8, 4), 256>>>(x, 0);
    k_xpart2  <<<dim3(4, 8, 4), 256>>>(x, 4);
    k_query   <<<dim3(2, 8),    256>>>(Wq);
    k_scores  <<<2048,          256>>>(mem);
    k_topk1   <<<dim3(TKB, 8),  256>>>();
    k_finish  <<<8,             128>>>(mem);
    k_w2ro    <<<dim3(4, 8, 2), 256>>>(Wq, Wo);
    k_attn_out<<<dim3(32, 8),   256>>>(x, out);
}

// round 10
// speedup vs baseline: 1.8932x; 1.4745x over previous
#include <cuda_runtime.h>
#include <math.h>

#define BB 8
#define SS 2048
#define HH 1024
#define NN 262144
#define DD 512
#define KK 8
#define TKB 128

__device__ float g_xpart[16 * BB * HH];     // [z16][b][h]
__device__ float g_qp[4 * BB * DD];         // [hc][b][d] partial queries
__device__ float g_q[BB * DD];
__device__ float g_scores[BB * NN];
__device__ float g_cand_v[BB * TKB * 8];
__device__ int   g_cand_i[BB * TKB * 8];
__device__ float g_Rt[BB * DD * KK];
__device__ float g_W2[BB * HH * KK];
__device__ float g_RO[BB * HH * KK];

__device__ __forceinline__ void fma2(unsigned long long& d,
                                     unsigned long long a, unsigned long long b) {
    asm("fma.rn.f32x2 %0, %1, %2, %0;" : "+l"(d) : "l"(a), "l"(b));
}
__device__ __forceinline__ void unpack2(unsigned long long v, float& lo, float& hi) {
    unsigned int l, h;
    asm("mov.b64 {%0, %1}, %2;" : "=r"(l), "=r"(h) : "l"(v));
    lo = __uint_as_float(l); hi = __uint_as_float(h);
}

// ---------- Kernel A: partial sums of x over S (512 blocks, 16 slots x 128 rows) ----------
__global__ void k_xpart3(const float* __restrict__ x) {
    int h = blockIdx.x * 256 + threadIdx.x;  // grid.x = 4
    int b = blockIdx.y;
    int z = blockIdx.z;                       // 16 slots of 128 rows
    const float* xp = x + ((size_t)b * SS + (size_t)z * 128) * HH + h;
    float s0 = 0.f, s1 = 0.f, s2 = 0.f, s3 = 0.f, s4 = 0.f, s5 = 0.f, s6 = 0.f, s7 = 0.f;
#pragma unroll 4
    for (int i = 0; i < 128; i += 8) {
        s0 += xp[(size_t)(i + 0) * HH];
        s1 += xp[(size_t)(i + 1) * HH];
        s2 += xp[(size_t)(i + 2) * HH];
        s3 += xp[(size_t)(i + 3) * HH];
        s4 += xp[(size_t)(i + 4) * HH];
        s5 += xp[(size_t)(i + 5) * HH];
        s6 += xp[(size_t)(i + 6) * HH];
        s7 += xp[(size_t)(i + 7) * HH];
    }
    g_xpart[(z * BB + b) * HH + h] = ((s0 + s1) + (s2 + s3)) + ((s4 + s5) + (s6 + s7));
}

// ---------- Kernel B: partial q over 256-h chunks (64 blocks) ----------
__global__ void __launch_bounds__(256) k_queryp(const float* __restrict__ Wq) {
    __shared__ float xs[256];
    int tid = threadIdx.x;
    int b = blockIdx.y, hc = blockIdx.z;     // hc in 0..3
    // xs[i] = sum over 16 z-slots of g_xpart[z][b][hc*256+i]
    {
        float s = 0.0f;
#pragma unroll
        for (int z = 0; z < 16; z++)
            s += g_xpart[(z * BB + b) * HH + hc * 256 + tid];
        xs[tid] = s;
    }
    __syncthreads();

    int d = blockIdx.x * 256 + tid;          // grid.x = 2
    float a0 = 0.f, a1 = 0.f, a2 = 0.f, a3 = 0.f, a4 = 0.f, a5 = 0.f, a6 = 0.f, a7 = 0.f;
    const float* wq = Wq + (size_t)(hc * 256) * DD + d;
#pragma unroll 4
    for (int h = 0; h < 256; h += 8) {
        a0 += xs[h + 0] * wq[(size_t)(h + 0) * DD];
        a1 += xs[h + 1] * wq[(size_t)(h + 1) * DD];
        a2 += xs[h + 2] * wq[(size_t)(h + 2) * DD];
        a3 += xs[h + 3] * wq[(size_t)(h + 3) * DD];
        a4 += xs[h + 4] * wq[(size_t)(h + 4) * DD];
        a5 += xs[h + 5] * wq[(size_t)(h + 5) * DD];
        a6 += xs[h + 6] * wq[(size_t)(h + 6) * DD];
        a7 += xs[h + 7] * wq[(size_t)(h + 7) * DD];
    }
    g_qp[(hc * BB + b) * DD + d] = ((a0 + a1) + (a2 + a3)) + ((a4 + a5) + (a6 + a7));
}

// ---------- Kernel B2: q = sum of 4 partials ----------
__global__ void k_qsum() {
    int i = blockIdx.x * 256 + threadIdx.x;  // 16 blocks
    g_q[i] = (g_qp[i] + g_qp[BB * DD + i]) + (g_qp[2 * BB * DD + i] + g_qp[3 * BB * DD + i]);
}

// ---------- Kernel C: cosine scores v4 — d-paired f32x2, zero packing ----------
// 256 threads = 8 warps; warp = 4 groups of 8 lanes; group handles 2 rows.
// Block covers 64 rows; grid 4096. m float4 == two native f32x2 halves; q too.
// Per warp-j (1KB): 2 LDG.128 + 8 LDS.128 + 36 fma2 = 46 inst -> 0.045 inst/B.
__global__ void __launch_bounds__(256, 3) k_scores(const float* __restrict__ mem) {
    __shared__ ulonglong2 qd[BB * 128];   // [b][d4]: (x,y),(z,w) u64 pairs, 16KB
    __shared__ float s_out[BB * 64];      // [b][row-in-block], 2KB
    int tid = threadIdx.x;
    {
        const ulonglong2* q2 = (const ulonglong2*)g_q;
        for (int i = tid; i < BB * 128; i += 256) qd[i] = q2[i];
    }
    __syncthreads();

    int w = tid >> 5, lane = tid & 31;
    int g = lane >> 3, e = lane & 7;
    int rowloc = w * 8 + g * 2;
    size_t row0 = (size_t)blockIdx.x * 64 + rowloc;
    const ulonglong2* ma_p = (const ulonglong2*)(mem + row0 * DD);
    const ulonglong2* mb_p = (const ulonglong2*)(mem + (row0 + 1) * DD);

    unsigned long long acc2[2][8];
    unsigned long long nrm2[2];
    nrm2[0] = nrm2[1] = 0ull;
#pragma unroll
    for (int b = 0; b < 8; b++) { acc2[0][b] = 0ull; acc2[1][b] = 0ull; }

#pragma unroll 2
    for (int j = 0; j < 16; j++) {
        int d4 = e + 8 * j;
        ulonglong2 ma = ma_p[d4];   // row r0: (x,y),(z,w)
        ulonglong2 mb = mb_p[d4];   // row r0+1

        fma2(nrm2[0], ma.x, ma.x);
        fma2(nrm2[0], ma.y, ma.y);
        fma2(nrm2[1], mb.x, mb.x);
        fma2(nrm2[1], mb.y, mb.y);
#pragma unroll
        for (int b = 0; b < 8; b++) {
            ulonglong2 qv = qd[b * 128 + d4];
            fma2(acc2[0][b], ma.x, qv.x);
            fma2(acc2[0][b], ma.y, qv.y);
            fma2(acc2[1][b], mb.x, qv.x);
            fma2(acc2[1][b], mb.y, qv.y);
        }
    }

    // collapse d-pairs to scalars
    float acc[2][8], nrm[2];
#pragma unroll
    for (int r = 0; r < 2; r++) {
        float lo, hi;
        unpack2(nrm2[r], lo, hi);
        nrm[r] = lo + hi;
#pragma unroll
        for (int b = 0; b < 8; b++) {
            unpack2(acc2[r][b], lo, hi);
            acc[r][b] = lo + hi;
        }
    }
    // 3-round butterfly within each 8-lane group
#pragma unroll
    for (int off = 1; off <= 4; off <<= 1) {
#pragma unroll
        for (int r = 0; r < 2; r++) {
            nrm[r] += __shfl_xor_sync(0xffffffffu, nrm[r], off);
#pragma unroll
            for (int b = 0; b < 8; b++)
                acc[r][b] += __shfl_xor_sync(0xffffffffu, acc[r][b], off);
        }
    }
    if (e == 0) {
#pragma unroll
        for (int r = 0; r < 2; r++) {
            float inv = 1.0f / (sqrtf(nrm[r]) + 1e-8f);
#pragma unroll
            for (int b = 0; b < 8; b++)
                s_out[b * 64 + rowloc + r] = acc[r][b] * inv;
        }
    }
    __syncthreads();
    if (tid < 128) {
        int b = tid >> 4, seg = tid & 15;
        *(float4*)&g_scores[(size_t)b * NN + (size_t)blockIdx.x * 64 + seg * 4] =
            *(const float4*)&s_out[b * 64 + seg * 4];
    }
}

// ---------- Kernel D1: stage-1 top-8 ----------
__global__ void __launch_bounds__(256) k_topk1() {
    __shared__ float sv[256 * 8];
    __shared__ int   si[256 * 8];
    int b = blockIdx.y, blk = blockIdx.x, tid = threadIdx.x;
    int base = blk * (NN / TKB);
    const float4* s4 = (const float4*)(g_scores + (size_t)b * NN + base);

    float vals[8];
    int idxs[8];
#pragma unroll
    for (int i = 0; i < 8; i++) { vals[i] = -3.4e38f; idxs[i] = 0; }
    float vmin = -3.4e38f;

#pragma unroll
    for (int it = 0; it < 2; it++) {
        int f = tid + it * 256;
        float4 v4 = s4[f];
        int n0 = base + f * 4;
        float vv[4] = {v4.x, v4.y, v4.z, v4.w};
#pragma unroll
        for (int c = 0; c < 4; c++) {
            float v = vv[c];
            if (v > vmin) {
                vals[7] = v; idxs[7] = n0 + c;
#pragma unroll
                for (int p = 7; p >= 1; p--) {
                    if (vals[p] > vals[p - 1]) {
                        float tv = vals[p]; vals[p] = vals[p - 1]; vals[p - 1] = tv;
                        int ti = idxs[p]; idxs[p] = idxs[p - 1]; idxs[p - 1] = ti;
                    }
                }
                vmin = vals[7];
            }
        }
    }
#pragma unroll
    for (int i = 0; i < 8; i++) { sv[tid * 8 + i] = vals[i]; si[tid * 8 + i] = idxs[i]; }

    for (int stride = 128; stride >= 1; stride >>= 1) {
        __syncthreads();
        if (tid < stride) {
            float ov[8]; int oi[8];
            int ia = 0, ib2 = 0;
#pragma unroll
            for (int o = 0; o < 8; o++) {
                float va = sv[tid * 8 + ia];
                float vb = sv[(tid + stride) * 8 + ib2];
                if (va >= vb) { ov[o] = va; oi[o] = si[tid * 8 + ia]; ia++; }
                else          { ov[o] = vb; oi[o] = si[(tid + stride) * 8 + ib2]; ib2++; }
            }
#pragma unroll
            for (int o = 0; o < 8; o++) { sv[tid * 8 + o] = ov[o]; si[tid * 8 + o] = oi[o]; }
        }
    }
    __syncthreads();
    if (tid < 8) {
        g_cand_v[(b * TKB + blk) * 8 + tid] = sv[tid];
        g_cand_i[(b * TKB + blk) * 8 + tid] = si[tid];
    }
}

// ---------- Kernel D2+E1 fused: final merge + gather + normalize ----------
__global__ void __launch_bounds__(128) k_finish(const float* __restrict__ mem) {
    __shared__ float sv[128 * 8];
    __shared__ int   si[128 * 8];
    __shared__ int   s_idx[8];
    int b = blockIdx.x, tid = threadIdx.x;
#pragma unroll
    for (int i = 0; i < 8; i++) {
        sv[tid * 8 + i] = g_cand_v[(b * TKB + tid) * 8 + i];
        si[tid * 8 + i] = g_cand_i[(b * TKB + tid) * 8 + i];
    }
    for (int stride = 64; stride >= 1; stride >>= 1) {
        __syncthreads();
        if (tid < stride) {
            float ov[8]; int oi[8];
            int ia = 0, ib2 = 0;
#pragma unroll
            for (int o = 0; o < 8; o++) {
                float va = sv[tid * 8 + ia];
                float vb = sv[(tid + stride) * 8 + ib2];
                if (va >= vb) { ov[o] = va; oi[o] = si[tid * 8 + ia]; ia++; }
                else          { ov[o] = vb; oi[o] = si[(tid + stride) * 8 + ib2]; ib2++; }
            }
#pragma unroll
            for (int o = 0; o < 8; o++) { sv[tid * 8 + o] = ov[o]; si[tid * 8 + o] = oi[o]; }
        }
    }
    __syncthreads();
    if (tid < 8) s_idx[tid] = si[tid];
    __syncthreads();

    int w = tid >> 5, lane = tid & 31;
#pragma unroll
    for (int kk = 0; kk < 2; kk++) {
        int k = w * 2 + kk;
        int row = s_idx[k];
        const float4* r4 = (const float4*)(mem + (size_t)row * DD);
        float4 v[4];
        float nr = 0.0f;
#pragma unroll
        for (int jj = 0; jj < 4; jj++) {
            v[jj] = r4[lane + 32 * jj];
            nr += v[jj].x * v[jj].x + v[jj].y * v[jj].y
                + v[jj].z * v[jj].z + v[jj].w * v[jj].w;
        }
#pragma unroll
        for (int off = 16; off; off >>= 1)
            nr += __shfl_xor_sync(0xffffffffu, nr, off);
        float inv = 1.0f / (sqrtf(nr) + 1e-8f);
        float* Rt = g_Rt + (size_t)b * DD * 8;
#pragma unroll
        for (int jj = 0; jj < 4; jj++) {
            int d0 = (lane + 32 * jj) * 4;
            Rt[(d0 + 0) * 8 + k] = v[jj].x * inv;
            Rt[(d0 + 1) * 8 + k] = v[jj].y * inv;
            Rt[(d0 + 2) * 8 + k] = v[jj].z * inv;
            Rt[(d0 + 3) * 8 + k] = v[jj].w * inv;
        }
    }
}

// ---------- Kernel E2+E3 fused ----------
__global__ void __launch_bounds__(256) k_w2ro(const float* __restrict__ Wq,
                                              const float* __restrict__ Wo) {
    __shared__ float4 R_sh[DD * 2];
    int b = blockIdx.y;
    const float4* Rt4 = (const float4*)(g_Rt + (size_t)b * DD * 8);
    for (int i = threadIdx.x; i < DD * 2; i += 256) R_sh[i] = Rt4[i];
    __syncthreads();

    int h = blockIdx.x * 256 + threadIdx.x;
    float acc[8];
#pragma unroll
    for (int k = 0; k < 8; k++) acc[k] = 0.0f;

    if (blockIdx.z == 0) {
        const float4* wq4 = (const float4*)(Wq + (size_t)h * DD);
#pragma unroll 2
        for (int dd = 0; dd < DD / 4; dd++) {
            float4 wv4 = wq4[dd];
            float wv[4] = {wv4.x, wv4.y, wv4.z, wv4.w};
#pragma unroll
            for (int c = 0; c < 4; c++) {
                float4 r0 = R_sh[(dd * 4 + c) * 2];
                float4 r1 = R_sh[(dd * 4 + c) * 2 + 1];
                acc[0] += wv[c] * r0.x; acc[1] += wv[c] * r0.y;
                acc[2] += wv[c] * r0.z; acc[3] += wv[c] * r0.w;
                acc[4] += wv[c] * r1.x; acc[5] += wv[c] * r1.y;
                acc[6] += wv[c] * r1.z; acc[7] += wv[c] * r1.w;
            }
        }
        const float scale = 0.044194173824159216f;  // 1/sqrt(512)
        float4* o = (float4*)(g_W2 + ((size_t)b * HH + h) * 8);
        o[0] = make_float4(acc[0] * scale, acc[1] * scale, acc[2] * scale, acc[3] * scale);
        o[1] = make_float4(acc[4] * scale, acc[5] * scale, acc[6] * scale, acc[7] * scale);
    } else {
#pragma unroll 4
        for (int d = 0; d < DD; d++) {
            float wo = Wo[(size_t)d * HH + h];
            float4 r0 = R_sh[d * 2];
            float4 r1 = R_sh[d * 2 + 1];
            acc[0] += wo * r0.x; acc[1] += wo * r0.y; acc[2] += wo * r0.z; acc[3] += wo * r0.w;
            acc[4] += wo * r1.x; acc[5] += wo * r1.y; acc[6] += wo * r1.z; acc[7] += wo * r1.w;
        }
        float4* o = (float4*)(g_RO + ((size_t)b * HH + h) * 8);
        o[0] = make_float4(acc[0], acc[1], acc[2], acc[3]);
        o[1] = make_float4(acc[4], acc[5], acc[6], acc[7]);
    }
}

// ---------- Kernel F (fused): logits -> softmax -> out ----------
__global__ void __launch_bounds__(256) k_attn_out(const float* __restrict__ x,
                                                  float* __restrict__ out) {
    __shared__ float W2p[HH * 9];
    __shared__ float attn_sh[64 * 8];
    int b = blockIdx.y;
    const float* W2g = g_W2 + (size_t)b * HH * 8;
    for (int i = threadIdx.x; i < HH * 8; i += 256) {
        int h = i >> 3, k = i & 7;
        W2p[h * 9 + k] = W2g[i];
    }
    __syncthreads();

    int lane = threadIdx.x & 31, warp = threadIdx.x >> 5;
    int tok0 = blockIdx.x * 64 + warp * 8;
    const float* xb = x + ((size_t)b * SS + tok0) * HH;

    float lp[8][8];
#pragma unroll
    for (int t = 0; t < 8; t++)
#pragma unroll
        for (int k = 0; k < 8; k++) lp[t][k] = 0.0f;

#pragma unroll 4
    for (int i = 0; i < 32; i++) {
        int h = lane + 32 * i;
        float w2v[8];
#pragma unroll
        for (int k = 0; k < 8; k++) w2v[k] = W2p[h * 9 + k];
#pragma unroll
        for (int t = 0; t < 8; t++) {
            float xv = xb[(size_t)t * HH + h];
#pragma unroll
            for (int k = 0; k < 8; k++) lp[t][k] += xv * w2v[k];
        }
    }
#pragma unroll
    for (int off = 16; off; off >>= 1)
#pragma unroll
        for (int t = 0; t < 8; t++)
#pragma unroll
            for (int k = 0; k < 8; k++)
                lp[t][k] += __shfl_xor_sync(0xffffffffu, lp[t][k], off);

#pragma unroll
    for (int t = 0; t < 8; t++) {
        float l[8];
        float m = -3.4e38f;
#pragma unroll
        for (int k = 0; k < 8; k++) { l[k] = lp[t][k]; m = fmaxf(m, l[k]); }
        float s = 0.0f;
#pragma unroll
        for (int k = 0; k < 8; k++) { l[k] = __expf(l[k] - m); s += l[k]; }
        float inv = 1.0f / s;
        if (lane == t) {
            float4* a4 = (float4*)&attn_sh[(warp * 8 + t) * 8];
            a4[0] = make_float4(l[0] * inv, l[1] * inv, l[2] * inv, l[3] * inv);
            a4[1] = make_float4(l[4] * inv, l[5] * inv, l[6] * inv, l[7] * inv);
        }
    }
    __syncthreads();

    float att[8][8];
#pragma unroll
    for (int t = 0; t < 8; t++)
#pragma unroll
        for (int k = 0; k < 8; k++) att[t][k] = attn_sh[(warp * 8 + t) * 8 + k];

    const float4* ROg = (const float4*)(g_RO + (size_t)b * HH * 8);
    float* ob = out + ((size_t)b * SS + tok0) * HH;

#pragma unroll 2
    for (int i = 0; i < 32; i++) {
        int h = lane + 32 * i;
        float4 r0 = __ldg(&ROg[h * 2]);
        float4 r1 = __ldg(&ROg[h * 2 + 1]);
        float ro[8] = {r0.x, r0.y, r0.z, r0.w, r1.x, r1.y, r1.z, r1.w};
#pragma unroll
        for (int t = 0; t < 8; t++) {
            float o = xb[(size_t)t * HH + h];
#pragma unroll
            for (int k = 0; k < 8; k++) o += att[t][k] * ro[k];
            ob[(size_t)t * HH + h] = o;
        }
    }
}

// ---------- launch (scores = 4th launch for the ncu capture slot) ----------
extern "C" void kernel_launch(void* const* d_in, const int* in_sizes, int n_in,
                              void* d_out, int out_size) {
    const float* x   = (const float*)d_in[0];
    const float* mem = (const float*)d_in[1];
    const float* Wq  = (const float*)d_in[2];
    const float* Wo  = (const float*)d_in[3];
    float* out = (float*)d_out;

    k_xpart3  <<<dim3(4, 8, 16), 256>>>(x);
    k_queryp  <<<dim3(2, 8, 4),  256>>>(Wq);
    k_qsum    <<<16,             256>>>();
    k_scores  <<<4096,           256>>>(mem);
    k_topk1   <<<dim3(TKB, 8),   256>>>();
    k_finish  <<<8,              128>>>(mem);
    k_w2ro    <<<dim3(4, 8, 2),  256>>>(Wq, Wo);
    k_attn_out<<<dim3(32, 8),    256>>>(x, out);
}